// round 16
// baseline (speedup 1.0000x reference)
#include <cuda_runtime.h>
#include <stdint.h>
#include <math.h>

#define NN 4096
#define HH 64
#define XDIM 200
#define EE 131072
#define CAP 96

#define WOFF    8
#define POOLOFF 524296
#define SRCOFF  524360
#define NSOFF   524424

__constant__ int c_src[10] = {0,1,2,3,1,0,1,2,1,3};
__constant__ int c_dst[10] = {0,1,2,3,0,1,2,1,3,1};

// agg/gemm op table (42 rows)
__constant__ int t_ki[42] = {0,1,2,3, 0,1,2,3, 0,1,2,3,4,5,6,7,8,9,
                             0,1,2,3,4,5,6,7,8,9, 0,1,2,3, 0,1,2,3,4,5,6,7,8,9};
__constant__ int t_at[42] = {0,0,0,0, 0,0,0,0, 1,1,1,1,0,0,0,0,0,0,
                             1,1,1,1,0,0,0,0,0,0, 1,1,1,1, 0,0,0,0,0,0,0,0,0,0};
__constant__ int t_in[42] = {0,0,0,0, 1,1,1,1, 0,0,0,0,0,0,0,0,0,0,
                             2,2,2,2,2,2,2,2,2,2, 3,3,3,3, 4,4,4,4,4,4,4,4,4,4};
__constant__ int t_slot[42]={0,1,2,3, 14,15,16,17, 4,5,6,7,8,9,10,11,12,13,
                             14,15,16,17,18,19,20,21,22,23, 24,25,26,27,
                             28,29,30,31,32,33,34,35,36,37};

__constant__ int cmb_cnt[4][3][5] = {
  {{1,1,1,1,0},{0,0,0,0,0},{0,0,0,0,0}},
  {{1,1,1,1,0},{0,0,0,0,0},{0,0,0,0,0}},
  {{2,4,2,2,0},{1,1,1,1,0},{2,4,2,2,0}},
  {{2,4,2,2,0},{1,1,1,1,0},{2,4,2,2,0}}};
__constant__ int cmb_slot[4][3][5][4] = {
  {{{0,0,0,0},{1,0,0,0},{2,0,0,0},{3,0,0,0},{0,0,0,0}},
   {{0,0,0,0},{0,0,0,0},{0,0,0,0},{0,0,0,0},{0,0,0,0}},
   {{0,0,0,0},{0,0,0,0},{0,0,0,0},{0,0,0,0},{0,0,0,0}}},
  {{{14,0,0,0},{15,0,0,0},{16,0,0,0},{17,0,0,0},{0,0,0,0}},
   {{0,0,0,0},{0,0,0,0},{0,0,0,0},{0,0,0,0},{0,0,0,0}},
   {{0,0,0,0},{0,0,0,0},{0,0,0,0},{0,0,0,0},{0,0,0,0}}},
  {{{4,8,0,0},{5,9,11,13},{6,10,0,0},{7,12,0,0},{0,0,0,0}},
   {{4,0,0,0},{5,0,0,0},{6,0,0,0},{7,0,0,0},{0,0,0,0}},
   {{0,8,0,0},{1,9,11,13},{2,10,0,0},{3,12,0,0},{0,0,0,0}}},
  {{{14,18,0,0},{15,19,21,23},{16,20,0,0},{17,22,0,0},{0,0,0,0}},
   {{24,0,0,0},{25,0,0,0},{26,0,0,0},{27,0,0,0},{0,0,0,0}},
   {{28,32,0,0},{29,33,35,37},{30,34,0,0},{31,36,0,0},{0,0,0,0}}}};

__device__ float  g_h0[5*NN*HH];
__device__ float  g_hl0[5*NN*HH];
__device__ float  g_h1[5*NN*HH];
__device__ float  g_hv[3*5*NN*HH];
__device__ float  g_A [38*NN*HH];
__device__ float  g_M [38*NN*HH];
__device__ float  g_ww[4*EE];
__device__ float  g_uf[4*NN], g_vf[4*NN];
__device__ float  g_epredf[4*EE];
__device__ int    g_asrc[10*NN*CAP];
__device__ int    g_aeid[10*NN*CAP];
__device__ int    g_acnt[10*NN];
__device__ int    g_spk[4*NN*CAP];
__device__ int    g_scnt[4*NN];
__device__ int    g_selcol[4*NN*16];
__device__ int    g_selcnt[4*NN];
__device__ int    g_cutoff[4*NN];

struct Ptrs5  { const float* p[5]; };
struct IPtrs5 { const int* p[5]; };
struct EPtrs  { const int* e[10]; };

// ---------------- threefry2x32 (JAX-exact) ----------------
__device__ __forceinline__ uint32_t rotl32(uint32_t v, int s){ return (v<<s)|(v>>(32-s)); }

__device__ __forceinline__ void threefry(uint32_t k0, uint32_t k1,
                                         uint32_t x0, uint32_t x1,
                                         uint32_t& o0, uint32_t& o1){
  uint32_t ks2 = k0 ^ k1 ^ 0x1BD11BDAu;
  x0 += k0; x1 += k1;
  x0+=x1; x1=rotl32(x1,13); x1^=x0;
  x0+=x1; x1=rotl32(x1,15); x1^=x0;
  x0+=x1; x1=rotl32(x1,26); x1^=x0;
  x0+=x1; x1=rotl32(x1, 6); x1^=x0;
  x0+=k1; x1+=ks2+1u;
  x0+=x1; x1=rotl32(x1,17); x1^=x0;
  x0+=x1; x1=rotl32(x1,29); x1^=x0;
  x0+=x1; x1=rotl32(x1,16); x1^=x0;
  x0+=x1; x1=rotl32(x1,24); x1^=x0;
  x0+=ks2; x1+=k0+2u;
  x0+=x1; x1=rotl32(x1,13); x1^=x0;
  x0+=x1; x1=rotl32(x1,15); x1^=x0;
  x0+=x1; x1=rotl32(x1,26); x1^=x0;
  x0+=x1; x1=rotl32(x1, 6); x1^=x0;
  x0+=k0; x1+=k1+3u;
  x0+=x1; x1=rotl32(x1,17); x1^=x0;
  x0+=x1; x1=rotl32(x1,29); x1^=x0;
  x0+=x1; x1=rotl32(x1,16); x1^=x0;
  x0+=x1; x1=rotl32(x1,24); x1^=x0;
  x0+=k1; x1+=ks2+4u;
  x0+=x1; x1=rotl32(x1,13); x1^=x0;
  x0+=x1; x1=rotl32(x1,15); x1^=x0;
  x0+=x1; x1=rotl32(x1,26); x1^=x0;
  x0+=x1; x1=rotl32(x1, 6); x1^=x0;
  x0+=ks2; x1+=k0+5u;
  o0=x0; o1=x1;
}

__device__ __forceinline__ float gumbel_at(uint32_t k0, uint32_t k1, uint32_t p){
  uint32_t o0,o1;
  threefry(k0,k1, 0u, p, o0,o1);
  uint32_t b = o0 ^ o1;
  float f = __uint_as_float((b>>9)|0x3f800000u) - 1.0f;
  const float mn = 1e-6f;
  const float mx = (float)(1.0 - 1e-6);
  float span = __fadd_rn(mx, -mn);
  float u = __fadd_rn(__fmul_rn(f, span), mn);
  u = fmaxf(mn, u);
  return -logf(-logf(u));
}

// ---------------- direct-bin CSR build (fixed capacity) ----------------

__global__ void k_zeroAll(){
  int i = blockIdx.x*256 + threadIdx.x;
  if (i < 10*NN) g_acnt[i] = 0;
  if (i < 4*NN)  g_scnt[i] = 0;
}

__global__ void k_binAll(EPtrs es){
  int b = blockIdx.y;
  int j = blockIdx.x*256 + threadIdx.x;
  if (j >= EE) return;
  if (b < 10){
    const int* ei = es.e[b];
    int src = ei[j], dst = ei[EE+j];
    int pos = atomicAdd(&g_acnt[b*NN + dst], 1);
    if (pos < CAP){
      g_asrc[((size_t)b*NN + dst)*CAP + pos] = src;
      g_aeid[((size_t)b*NN + dst)*CAP + pos] = j;
    }
  } else {
    int ki = b-10;
    const int* ei = es.e[ki];
    int r = ei[j], c = ei[EE+j];
    int pos = atomicAdd(&g_scnt[ki*NN + r], 1);
    if (pos < CAP) g_spk[((size_t)ki*NN + r)*CAP + pos] = (c<<17) | j;
  }
}

__global__ void k_sortAll(){
  int b = blockIdx.y;
  int row = blockIdx.x*256 + threadIdx.x;
  if (row >= NN) return;
  if (b < 10){
    int n = g_acnt[b*NN+row]; if (n > CAP) n = CAP;
    int* eid = g_aeid + ((size_t)b*NN + row)*CAP;
    int* src = g_asrc + ((size_t)b*NN + row)*CAP;
    for (int i=1;i<n;i++){
      int e = eid[i], s = src[i];
      int j = i-1;
      while (j>=0 && eid[j] > e){ eid[j+1]=eid[j]; src[j+1]=src[j]; j--; }
      eid[j+1]=e; src[j+1]=s;
    }
  } else {
    int ki = b-10;
    int n = g_scnt[ki*NN+row]; if (n > CAP) n = CAP;
    int* pk = g_spk + ((size_t)ki*NN + row)*CAP;
    for (int i=1;i<n;i++){
      int x = pk[i]; int j = i-1;
      while (j>=0 && pk[j] > x){ pk[j+1]=pk[j]; j--; }
      pk[j+1]=x;
    }
  }
}

// ---------------- GNN ----------------

__global__ void k_input(Ptrs5 xs, const float* w_in, const float* b_in){
  __shared__ float sx[XDIM];
  int d = blockIdx.y;
  int row = blockIdx.x;
  int col = threadIdx.x;        // 64 threads
  const float* x = xs.p[d] + (size_t)row*XDIM;
  for (int i=col;i<XDIM;i+=64) sx[i] = x[i];
  __syncthreads();
  const float* w = w_in + (size_t)d*XDIM*HH + col;
  float acc = 0.f;
  for (int k=0;k<XDIM;k++) acc = fmaf(sx[k], w[k*HH], acc);
  g_h0[(size_t)d*NN*HH + row*HH + col] = fmaxf(acc + b_in[d*HH+col], 0.f);
}

// aggregation: 16 threads/node float4, edge loop unrolled x8
__global__ void k_aggU(int rowOff){
  int e = rowOff + blockIdx.y;
  int ki = t_ki[e];
  int node = blockIdx.x*16 + (threadIdx.x>>4);
  int c4 = (threadIdx.x & 15)*4;
  int n = g_acnt[ki*NN+node]; if (n > CAP) n = CAP;
  const int* srcp = g_asrc + ((size_t)ki*NN + node)*CAP;
  const int* eidp = g_aeid + ((size_t)ki*NN + node)*CAP;
  const float* hbase;
  int insel = t_in[e];
  if (insel==0) hbase = g_h0;
  else if (insel==1) hbase = g_hl0;
  else hbase = g_hv + (size_t)(insel-2)*5*NN*HH;
  const float* hb = hbase + (size_t)c_src[ki]*NN*HH;
  float4 s = make_float4(0.f,0.f,0.f,0.f);
  int i = 0;
  if (t_at[e]){
    const float* wwp = g_ww + (size_t)ki*EE;
    for (; i+8<=n; i+=8){
      int si[8]; float wv[8];
      #pragma unroll
      for (int u=0;u<8;u++){ si[u]=__ldg(&srcp[i+u]); }
      #pragma unroll
      for (int u=0;u<8;u++){ wv[u]=__ldg(&wwp[__ldg(&eidp[i+u])]); }
      float4 av[8];
      #pragma unroll
      for (int u=0;u<8;u++) av[u] = *(const float4*)&hb[(size_t)si[u]*HH + c4];
      #pragma unroll
      for (int u=0;u<8;u++){
        s.x=fmaf(av[u].x,wv[u],s.x); s.y=fmaf(av[u].y,wv[u],s.y);
        s.z=fmaf(av[u].z,wv[u],s.z); s.w=fmaf(av[u].w,wv[u],s.w);
      }
    }
    for (; i<n; i++){
      int sc=__ldg(&srcp[i]);
      float w=__ldg(&wwp[__ldg(&eidp[i])]);
      float4 a = *(const float4*)&hb[(size_t)sc*HH + c4];
      s.x=fmaf(a.x,w,s.x); s.y=fmaf(a.y,w,s.y); s.z=fmaf(a.z,w,s.z); s.w=fmaf(a.w,w,s.w);
    }
  } else {
    for (; i+8<=n; i+=8){
      int si[8];
      #pragma unroll
      for (int u=0;u<8;u++) si[u]=__ldg(&srcp[i+u]);
      float4 av[8];
      #pragma unroll
      for (int u=0;u<8;u++) av[u] = *(const float4*)&hb[(size_t)si[u]*HH + c4];
      #pragma unroll
      for (int u=0;u<8;u++){
        s.x+=av[u].x; s.y+=av[u].y; s.z+=av[u].z; s.w+=av[u].w;
      }
    }
    for (; i<n; i++){
      int sc=__ldg(&srcp[i]);
      float4 a = *(const float4*)&hb[(size_t)sc*HH + c4];
      s.x+=a.x; s.y+=a.y; s.z+=a.z; s.w+=a.w;
    }
  }
  *(float4*)&g_A[(size_t)t_slot[e]*NN*HH + node*HH + c4] = s;
}

// M[slot] = A[slot] @ W[ki]; W column in registers
__global__ void __launch_bounds__(256) k_gemm(int rowOff, const float* wl){
  __shared__ float sW[4096];
  int e = rowOff + blockIdx.y;
  int ki = t_ki[e];
  int slot = t_slot[e];
  for (int i=threadIdx.x;i<4096;i+=256) sW[i] = wl[(size_t)ki*4096 + i];
  __syncthreads();
  int colt = threadIdx.x & 63;
  int rb   = threadIdx.x >> 6;
  float w[64];
  #pragma unroll
  for (int k=0;k<64;k++) w[k] = sW[k*64+colt];
  const float* Ab = g_A + (size_t)slot*NN*HH;
  float* Mb = g_M + (size_t)slot*NN*HH;
  int row0 = blockIdx.x*64;
  for (int q=0;q<16;q++){
    int row = row0 + q*4 + rb;
    const float4* Ar = (const float4*)&Ab[(size_t)row*HH];
    float acc = 0.f;
    #pragma unroll
    for (int k4=0;k4<16;k4++){
      float4 a = Ar[k4];
      acc = fmaf(a.x, w[4*k4+0], acc);
      acc = fmaf(a.y, w[4*k4+1], acc);
      acc = fmaf(a.z, w[4*k4+2], acc);
      acc = fmaf(a.w, w[4*k4+3], acc);
    }
    Mb[(size_t)row*HH + colt] = acc;
  }
}

// h_out = relu(base + sum M[slots])
__global__ void k_comb(int set, int baseSel, int outSel){
  int v = blockIdx.z, d = blockIdx.y;
  int i = blockIdx.x*256 + threadIdx.x;     // < NN*HH
  const float* base = (baseSel==0)? g_h0 : ((baseSel==1)? g_hl0 : g_hv + (size_t)v*5*NN*HH);
  float* outp = (outSel==0)? g_hl0 : ((outSel==1)? g_h1 : g_hv + (size_t)v*5*NN*HH);
  size_t off = (size_t)d*NN*HH + i;
  float s = base[off];
  int cnt = cmb_cnt[set][v][d];
  for (int j=0;j<cnt;j++)
    s += g_M[(size_t)cmb_slot[set][v][d][j]*NN*HH + i];
  outp[off] = fmaxf(s, 0.f);
}

// ---------------- edge sparsification (batched over 4 keys) ----------------

__global__ void k_uvB(const float* w_pred){
  int ki = blockIdx.y;
  int n = blockIdx.x*256 + threadIdx.x;
  if (n >= NN) return;
  const float* h = g_h1 + (size_t)ki*NN*HH + (size_t)n*HH;
  const float* wp = w_pred + ki*256;
  float a=0.f, b=0.f;
  for (int c=0;c<64;c++){
    float hv = h[c];
    a = fmaf(hv, wp[c*2],      a);
    b = fmaf(hv, wp[(64+c)*2], b);
  }
  g_uf[ki*NN+n]=a; g_vf[ki*NN+n]=b;
}

__global__ void k_predwB(EPtrs es, const float* b_pred){
  int ki = blockIdx.y;
  int j = blockIdx.x*256 + threadIdx.x;
  if (j >= EE) return;
  const int* ei = es.e[ki];
  int r = ei[j], c = ei[EE+j];
  g_epredf[(size_t)ki*EE + j] = (g_uf[ki*NN+r] + g_vf[ki*NN+c]) + b_pred[ki*2];
}

__global__ void k_selectB(){
  int ki = blockIdx.y;
  int r = blockIdx.x*128 + threadIdx.x;
  if (r >= NN) return;
  uint32_t fk0, fk1;
  threefry(0u, 42u, 0u, (uint32_t)ki, fk0, fk1);

  int n = g_scnt[ki*NN+r]; if (n > CAP) n = CAP;
  const int* pk = g_spk + ((size_t)ki*NN + r)*CAP;
  const float* ep = g_epredf + (size_t)ki*EE;

  int mcol[CAP]; float mlg[CAP]; int m = 0;
  int i = 0;
  while (i < n){
    int c = pk[i] >> 17;
    float s = 0.f;
    while (i < n && (pk[i]>>17) == c){
      s = s + ep[pk[i] & 0x1FFFF];
      i++;
    }
    if (s > 0.0f){
      float g = gumbel_at(fk0, fk1, (uint32_t)r*4096u + (uint32_t)c);
      mcol[m] = c;
      mlg[m]  = s + g;
      m++;
    }
  }
  int tc = 0; int tcol[16]; float te[16];
  if (m > 0){
    float mx = mlg[0];
    for (int q=1;q<m;q++) mx = fmaxf(mx, mlg[q]);
    for (int q=0;q<m;q++){
      float E = expf(mlg[q]-mx);
      int C = mcol[q];
      if (tc==16 && !(E > te[15])) continue;
      int pos = (tc<16) ? tc++ : 15;
      while (pos>0 && te[pos-1] < E){ te[pos]=te[pos-1]; tcol[pos]=tcol[pos-1]; pos--; }
      te[pos]=E; tcol[pos]=C;
    }
  }
  int cut = -1;
  if (m < 16){
    int X = (16 - m) - 1;
    for (int q=0;q<m;q++) if (mcol[q] <= X) X++;
    cut = X;
  }
  g_selcnt[ki*NN+r] = tc;
  g_cutoff[ki*NN+r] = cut;
  for (int j=0;j<tc;j++) g_selcol[(ki*NN+r)*16+j] = tcol[j];
}

__global__ void k_edgewB(EPtrs es, float* out){
  int ki = blockIdx.y;
  int j = blockIdx.x*256 + threadIdx.x;
  if (j >= EE) return;
  const int* ei = es.e[ki];
  int r = ei[j], c = ei[EE+j];
  int cnt = g_selcnt[ki*NN+r];
  float w = 0.f;
  const int* sc = &g_selcol[(ki*NN+r)*16];
  for (int q=0;q<cnt;q++) if (sc[q] == c){ w = 1.0f; break; }
  if (w == 0.f && c <= g_cutoff[ki*NN+r]) w = 1.0f;
  g_ww[(size_t)ki*EE + j] = w;
  out[WOFF + (size_t)ki*EE + j] = w;
}

// ---------------- outputs ----------------

__global__ void k_pool(const int* idxp, const float* w_cls, const float* b_cls, float* out){
  __shared__ float p[64];
  __shared__ float lg[8];
  int t = threadIdx.x;
  int idx = *idxp;
  float v = g_hv[0*5*NN*HH + 1*NN*HH + (size_t)idx*HH + t];
  p[t] = v;
  out[POOLOFF + t] = v;
  __syncthreads();
  if (t < 8){
    float a = 0.f;
    for (int c=0;c<64;c++) a = fmaf(p[c], w_cls[c*8+t], a);
    lg[t] = a + b_cls[t];
  }
  __syncthreads();
  if (t == 0){
    float mx = lg[0];
    for (int i2=1;i2<8;i2++) mx = fmaxf(mx, lg[i2]);
    float Z = 0.f, ex[8];
    for (int i2=0;i2<8;i2++){ ex[i2] = expf(lg[i2]-mx); Z += ex[i2]; }
    for (int i2=0;i2<8;i2++) out[i2] = ex[i2]/Z;
  }
}

__global__ void k_srcpool(const int* idxp, float* out){
  int t = threadIdx.x;
  int idx = *idxp;
  out[SRCOFF + t] = g_hv[2*5*NN*HH + 1*NN*HH + (size_t)idx*HH + t];
}

__global__ void k_nodesub(IPtrs5 bs, float* out){
  int d = blockIdx.x >> 4;
  int g = blockIdx.x & 15;
  int c = threadIdx.x;
  const int* b = bs.p[d];
  int lo=0, hi=NN;
  while (lo<hi){ int mid=(lo+hi)>>1; if (b[mid]< g) lo=mid+1; else hi=mid; }
  int st = lo;
  lo=0; hi=NN;
  while (lo<hi){ int mid=(lo+hi)>>1; if (b[mid]<=g) lo=mid+1; else hi=mid; }
  int en = lo;
  const float* hb = g_hv + 1*5*NN*HH + (size_t)d*NN*HH;
  float acc = 0.f;
  for (int nn2=st; nn2<en; nn2++) acc += hb[(size_t)nn2*HH + c];
  out[NSOFF + (d*16+g)*64 + c] = acc;
}

// ---------------- host ----------------

extern "C" void kernel_launch(void* const* d_in, const int* in_sizes, int n_in,
                              void* d_out, int out_size){
  Ptrs5 xs;  for (int i=0;i<5;i++)  xs.p[i] = (const float*)d_in[i];
  EPtrs es;  for (int i=0;i<10;i++) es.e[i] = (const int*)d_in[5+i];
  IPtrs5 bb; for (int i=0;i<5;i++)  bb.p[i] = (const int*)d_in[15+i];
  const int*   idxp   = (const int*)  d_in[20];
  const float* w_in   = (const float*)d_in[21];
  const float* b_in   = (const float*)d_in[22];
  const float* w_msg  = (const float*)d_in[23];
  const float* w_pred = (const float*)d_in[24];
  const float* b_pred = (const float*)d_in[25];
  const float* w_cls  = (const float*)d_in[26];
  const float* b_cls  = (const float*)d_in[27];
  float* out = (float*)d_out;
  const float* wL0 = w_msg;
  const float* wL1 = w_msg + 10*64*64;

  // direct-bin CSR build (10 agg + 4 sel)
  k_zeroAll<<<160,256>>>();
  k_binAll<<<dim3(512,14),256>>>(es);
  k_sortAll<<<dim3(16,14),256>>>();

  // input transform
  k_input<<<dim3(4096,5),64>>>(xs, w_in, b_in);

  // Phase A: h1
  k_aggU<<<dim3(256,4),256>>>(0);
  k_gemm<<<dim3(64,4),256>>>(0, wL0);
  k_comb<<<dim3(1024,5,1),256>>>(0, 0, 0);
  k_aggU<<<dim3(256,4),256>>>(4);
  k_gemm<<<dim3(64,4),256>>>(4, wL1);
  k_comb<<<dim3(1024,5,1),256>>>(1, 1, 1);

  // edge sparsification
  k_uvB<<<dim3(16,4),256>>>(w_pred);
  k_predwB<<<dim3(512,4),256>>>(es, b_pred);
  k_selectB<<<dim3(32,4),128>>>();
  k_edgewB<<<dim3(512,4),256>>>(es, out);

  // Phase B layer 0
  k_aggU<<<dim3(256,10),256>>>(8);
  k_gemm<<<dim3(64,10),256>>>(8, wL0);
  k_comb<<<dim3(1024,5,3),256>>>(2, 0, 2);

  // Phase B layer 1
  k_aggU<<<dim3(256,24),256>>>(18);
  k_gemm<<<dim3(64,24),256>>>(18, wL1);
  k_comb<<<dim3(1024,5,3),256>>>(3, 2, 2);

  // outputs
  k_pool<<<1,64>>>(idxp, w_cls, b_cls, out);
  k_nodesub<<<80,64>>>(bb, out);
  k_srcpool<<<1,64>>>(idxp, out);
}

// round 17
// speedup vs baseline: 1.1629x; 1.1629x over previous
#include <cuda_runtime.h>
#include <stdint.h>
#include <math.h>

#define NN 4096
#define HH 64
#define XDIM 200
#define EE 131072

#define WOFF    8
#define POOLOFF 524296
#define SRCOFF  524360
#define NSOFF   524424

__constant__ int c_src[10] = {0,1,2,3,1,0,1,2,1,3};
__constant__ int c_dst[10] = {0,1,2,3,0,1,2,1,3,1};

// agg/gemm op table (42 rows)
__constant__ int t_ki[42] = {0,1,2,3, 0,1,2,3, 0,1,2,3,4,5,6,7,8,9,
                             0,1,2,3,4,5,6,7,8,9, 0,1,2,3, 0,1,2,3,4,5,6,7,8,9};
__constant__ int t_at[42] = {0,0,0,0, 0,0,0,0, 1,1,1,1,0,0,0,0,0,0,
                             1,1,1,1,0,0,0,0,0,0, 1,1,1,1, 0,0,0,0,0,0,0,0,0,0};
__constant__ int t_in[42] = {0,0,0,0, 1,1,1,1, 0,0,0,0,0,0,0,0,0,0,
                             2,2,2,2,2,2,2,2,2,2, 3,3,3,3, 4,4,4,4,4,4,4,4,4,4};
__constant__ int t_slot[42]={0,1,2,3, 14,15,16,17, 4,5,6,7,8,9,10,11,12,13,
                             14,15,16,17,18,19,20,21,22,23, 24,25,26,27,
                             28,29,30,31,32,33,34,35,36,37};

__constant__ int cmb_cnt[4][3][5] = {
  {{1,1,1,1,0},{0,0,0,0,0},{0,0,0,0,0}},
  {{1,1,1,1,0},{0,0,0,0,0},{0,0,0,0,0}},
  {{2,4,2,2,0},{1,1,1,1,0},{2,4,2,2,0}},
  {{2,4,2,2,0},{1,1,1,1,0},{2,4,2,2,0}}};
__constant__ int cmb_slot[4][3][5][4] = {
  {{{0,0,0,0},{1,0,0,0},{2,0,0,0},{3,0,0,0},{0,0,0,0}},
   {{0,0,0,0},{0,0,0,0},{0,0,0,0},{0,0,0,0},{0,0,0,0}},
   {{0,0,0,0},{0,0,0,0},{0,0,0,0},{0,0,0,0},{0,0,0,0}}},
  {{{14,0,0,0},{15,0,0,0},{16,0,0,0},{17,0,0,0},{0,0,0,0}},
   {{0,0,0,0},{0,0,0,0},{0,0,0,0},{0,0,0,0},{0,0,0,0}},
   {{0,0,0,0},{0,0,0,0},{0,0,0,0},{0,0,0,0},{0,0,0,0}}},
  {{{4,8,0,0},{5,9,11,13},{6,10,0,0},{7,12,0,0},{0,0,0,0}},
   {{4,0,0,0},{5,0,0,0},{6,0,0,0},{7,0,0,0},{0,0,0,0}},
   {{0,8,0,0},{1,9,11,13},{2,10,0,0},{3,12,0,0},{0,0,0,0}}},
  {{{14,18,0,0},{15,19,21,23},{16,20,0,0},{17,22,0,0},{0,0,0,0}},
   {{24,0,0,0},{25,0,0,0},{26,0,0,0},{27,0,0,0},{0,0,0,0}},
   {{28,32,0,0},{29,33,35,37},{30,34,0,0},{31,36,0,0},{0,0,0,0}}}};

__device__ float  g_h0[5*NN*HH];
__device__ float  g_hl0[5*NN*HH];
__device__ float  g_h1[5*NN*HH];
__device__ float  g_hv[3*5*NN*HH];
__device__ float  g_A [38*NN*HH];
__device__ float  g_M [38*NN*HH];
__device__ float  g_ww[4*EE];
__device__ float  g_uf[4*NN], g_vf[4*NN];
__device__ float  g_epredf[4*EE];
__device__ int    g_aoff[10*(NN+1)];
__device__ int    g_asrc[10*EE];
__device__ int    g_aeid[10*EE];
__device__ int    g_hist10[10*NN];
__device__ int    g_acur[10*NN];
__device__ int    g_soff[4*(NN+1)];
__device__ int    g_spk[4*EE];
__device__ int    g_hist4[4*NN];
__device__ int    g_scur[4*NN];
__device__ int    g_selcol[4*NN*16];
__device__ int    g_selcnt[4*NN];
__device__ int    g_cutoff[4*NN];

struct Ptrs5  { const float* p[5]; };
struct IPtrs5 { const int* p[5]; };
struct EPtrs  { const int* e[10]; };

// ---------------- threefry2x32 (JAX-exact) ----------------
__device__ __forceinline__ uint32_t rotl32(uint32_t v, int s){ return (v<<s)|(v>>(32-s)); }

__device__ __forceinline__ void threefry(uint32_t k0, uint32_t k1,
                                         uint32_t x0, uint32_t x1,
                                         uint32_t& o0, uint32_t& o1){
  uint32_t ks2 = k0 ^ k1 ^ 0x1BD11BDAu;
  x0 += k0; x1 += k1;
  x0+=x1; x1=rotl32(x1,13); x1^=x0;
  x0+=x1; x1=rotl32(x1,15); x1^=x0;
  x0+=x1; x1=rotl32(x1,26); x1^=x0;
  x0+=x1; x1=rotl32(x1, 6); x1^=x0;
  x0+=k1; x1+=ks2+1u;
  x0+=x1; x1=rotl32(x1,17); x1^=x0;
  x0+=x1; x1=rotl32(x1,29); x1^=x0;
  x0+=x1; x1=rotl32(x1,16); x1^=x0;
  x0+=x1; x1=rotl32(x1,24); x1^=x0;
  x0+=ks2; x1+=k0+2u;
  x0+=x1; x1=rotl32(x1,13); x1^=x0;
  x0+=x1; x1=rotl32(x1,15); x1^=x0;
  x0+=x1; x1=rotl32(x1,26); x1^=x0;
  x0+=x1; x1=rotl32(x1, 6); x1^=x0;
  x0+=k0; x1+=k1+3u;
  x0+=x1; x1=rotl32(x1,17); x1^=x0;
  x0+=x1; x1=rotl32(x1,29); x1^=x0;
  x0+=x1; x1=rotl32(x1,16); x1^=x0;
  x0+=x1; x1=rotl32(x1,24); x1^=x0;
  x0+=k1; x1+=ks2+4u;
  x0+=x1; x1=rotl32(x1,13); x1^=x0;
  x0+=x1; x1=rotl32(x1,15); x1^=x0;
  x0+=x1; x1=rotl32(x1,26); x1^=x0;
  x0+=x1; x1=rotl32(x1, 6); x1^=x0;
  x0+=ks2; x1+=k0+5u;
  o0=x0; o1=x1;
}

__device__ __forceinline__ float gumbel_at(uint32_t k0, uint32_t k1, uint32_t p){
  uint32_t o0,o1;
  threefry(k0,k1, 0u, p, o0,o1);
  uint32_t b = o0 ^ o1;
  float f = __uint_as_float((b>>9)|0x3f800000u) - 1.0f;
  const float mn = 1e-6f;
  const float mx = (float)(1.0 - 1e-6);
  float span = __fadd_rn(mx, -mn);
  float u = __fadd_rn(__fmul_rn(f, span), mn);
  u = fmaxf(mn, u);
  return -logf(-logf(u));
}

// ---------------- unified CSR build (10 agg-by-dst + 4 sel-by-src) ----------------

__global__ void k_zeroAll(){
  int i = blockIdx.x*256 + threadIdx.x;
  if (i < 10*NN) g_hist10[i] = 0;
  if (i < 4*NN)  g_hist4[i]  = 0;
}

__global__ void k_countAll(EPtrs es){
  int b = blockIdx.y;
  int j = blockIdx.x*256 + threadIdx.x;
  if (j >= EE) return;
  if (b < 10) atomicAdd(&g_hist10[b*NN + es.e[b][EE+j]], 1);
  else        atomicAdd(&g_hist4 [(b-10)*NN + es.e[b-10][j]], 1);
}

__global__ void k_scanAll(){
  __shared__ int sh[4096];
  __shared__ int part[1024];
  int b = blockIdx.x;
  const int* hist = (b<10)? (g_hist10 + b*NN) : (g_hist4 + (b-10)*NN);
  int* offs = (b<10)? (g_aoff + b*(NN+1)) : (g_soff + (b-10)*(NN+1));
  int* cur  = (b<10)? (g_acur + b*NN)     : (g_scur + (b-10)*NN);
  int t = threadIdx.x;
  for (int i=t;i<4096;i+=1024) sh[i]=hist[i];
  __syncthreads();
  int base = t*4;
  int s0 = sh[base];
  int s1 = s0 + sh[base+1];
  int s2 = s1 + sh[base+2];
  int s3 = s2 + sh[base+3];
  part[t] = s3;
  __syncthreads();
  for (int off=1; off<1024; off<<=1){
    int v = (t>=off)? part[t-off] : 0;
    __syncthreads();
    part[t] += v;
    __syncthreads();
  }
  int excl = (t>0)? part[t-1] : 0;
  offs[base]   = excl;
  offs[base+1] = excl + s0;
  offs[base+2] = excl + s1;
  offs[base+3] = excl + s2;
  cur[base]   = excl;
  cur[base+1] = excl + s0;
  cur[base+2] = excl + s1;
  cur[base+3] = excl + s2;
  if (t==1023) offs[4096] = excl + s3;
}

__global__ void k_binAll(EPtrs es){
  int b = blockIdx.y;
  int j = blockIdx.x*256 + threadIdx.x;
  if (j >= EE) return;
  if (b < 10){
    const int* ei = es.e[b];
    int src = ei[j], dst = ei[EE+j];
    int pos = atomicAdd(&g_acur[b*NN + dst], 1);
    g_asrc[(size_t)b*EE + pos] = src;
    g_aeid[(size_t)b*EE + pos] = j;
  } else {
    int ki = b-10;
    const int* ei = es.e[ki];
    int r = ei[j], c = ei[EE+j];
    int pos = atomicAdd(&g_scur[ki*NN + r], 1);
    g_spk[(size_t)ki*EE + pos] = (c<<17) | j;
  }
}

__global__ void k_sortAll(){
  int b = blockIdx.y;
  int row = blockIdx.x*256 + threadIdx.x;
  if (row >= NN) return;
  if (b < 10){
    int beg = g_aoff[b*(NN+1)+row], end = g_aoff[b*(NN+1)+row+1];
    int* eid = g_aeid + (size_t)b*EE;
    int* src = g_asrc + (size_t)b*EE;
    for (int i=beg+1;i<end;i++){
      int e = eid[i], s = src[i];
      int j = i-1;
      while (j>=beg && eid[j] > e){ eid[j+1]=eid[j]; src[j+1]=src[j]; j--; }
      eid[j+1]=e; src[j+1]=s;
    }
  } else {
    int ki = b-10;
    int beg = g_soff[ki*(NN+1)+row], end = g_soff[ki*(NN+1)+row+1];
    int* pk = g_spk + (size_t)ki*EE;
    for (int i=beg+1;i<end;i++){
      int x = pk[i]; int j = i-1;
      while (j>=beg && pk[j] > x){ pk[j+1]=pk[j]; j--; }
      pk[j+1]=x;
    }
  }
}

// ---------------- GNN ----------------

// 16 rows per block, 4 rows per thread sharing W registers; per-row k-order unchanged
__global__ void __launch_bounds__(256) k_input(Ptrs5 xs, const float* w_in, const float* b_in){
  __shared__ float sx[16*XDIM];
  int d = blockIdx.y;
  int row0 = blockIdx.x*16;
  int col = threadIdx.x & 63;
  int rq  = threadIdx.x >> 6;       // 0..3
  const float* xbase = xs.p[d] + (size_t)row0*XDIM;
  for (int i=threadIdx.x; i<16*XDIM; i+=256) sx[i] = xbase[i];
  __syncthreads();
  const float* w = w_in + (size_t)d*XDIM*HH + col;
  float acc0=0.f, acc1=0.f, acc2=0.f, acc3=0.f;
  const float* x0 = &sx[(rq*4+0)*XDIM];
  const float* x1 = &sx[(rq*4+1)*XDIM];
  const float* x2 = &sx[(rq*4+2)*XDIM];
  const float* x3 = &sx[(rq*4+3)*XDIM];
  #pragma unroll 2
  for (int k=0;k<XDIM;k+=4){
    float w0=__ldg(&w[(k+0)*HH]);
    float w1=__ldg(&w[(k+1)*HH]);
    float w2=__ldg(&w[(k+2)*HH]);
    float w3=__ldg(&w[(k+3)*HH]);
    float4 a0 = *(const float4*)&x0[k];
    float4 a1 = *(const float4*)&x1[k];
    float4 a2 = *(const float4*)&x2[k];
    float4 a3 = *(const float4*)&x3[k];
    acc0=fmaf(a0.x,w0,acc0); acc0=fmaf(a0.y,w1,acc0); acc0=fmaf(a0.z,w2,acc0); acc0=fmaf(a0.w,w3,acc0);
    acc1=fmaf(a1.x,w0,acc1); acc1=fmaf(a1.y,w1,acc1); acc1=fmaf(a1.z,w2,acc1); acc1=fmaf(a1.w,w3,acc1);
    acc2=fmaf(a2.x,w0,acc2); acc2=fmaf(a2.y,w1,acc2); acc2=fmaf(a2.z,w2,acc2); acc2=fmaf(a2.w,w3,acc2);
    acc3=fmaf(a3.x,w0,acc3); acc3=fmaf(a3.y,w1,acc3); acc3=fmaf(a3.z,w2,acc3); acc3=fmaf(a3.w,w3,acc3);
  }
  float bv = b_in[d*HH+col];
  size_t ob = (size_t)d*NN*HH + (size_t)(row0 + rq*4)*HH + col;
  g_h0[ob]        = fmaxf(acc0 + bv, 0.f);
  g_h0[ob+HH]     = fmaxf(acc1 + bv, 0.f);
  g_h0[ob+2*HH]   = fmaxf(acc2 + bv, 0.f);
  g_h0[ob+3*HH]   = fmaxf(acc3 + bv, 0.f);
}

// aggregation: 16 threads/node float4, edge loop unrolled x4 for MLP
__global__ void k_aggU(int rowOff){
  int e = rowOff + blockIdx.y;
  int ki = t_ki[e];
  int node = blockIdx.x*16 + (threadIdx.x>>4);
  int c4 = (threadIdx.x & 15)*4;
  int beg = g_aoff[ki*(NN+1)+node], end = g_aoff[ki*(NN+1)+node+1];
  const int* srcp = g_asrc + (size_t)ki*EE;
  const int* eidp = g_aeid + (size_t)ki*EE;
  const float* hbase;
  int insel = t_in[e];
  if (insel==0) hbase = g_h0;
  else if (insel==1) hbase = g_hl0;
  else hbase = g_hv + (size_t)(insel-2)*5*NN*HH;
  const float* hb = hbase + (size_t)c_src[ki]*NN*HH;
  float4 s = make_float4(0.f,0.f,0.f,0.f);
  int i = beg;
  if (t_at[e]){
    const float* wwp = g_ww + (size_t)ki*EE;
    for (; i+4<=end; i+=4){
      int s0=__ldg(&srcp[i]),   s1=__ldg(&srcp[i+1]);
      int s2=__ldg(&srcp[i+2]), s3=__ldg(&srcp[i+3]);
      float w0=__ldg(&wwp[__ldg(&eidp[i])]),   w1=__ldg(&wwp[__ldg(&eidp[i+1])]);
      float w2=__ldg(&wwp[__ldg(&eidp[i+2])]), w3=__ldg(&wwp[__ldg(&eidp[i+3])]);
      float4 a0 = *(const float4*)&hb[(size_t)s0*HH + c4];
      float4 a1 = *(const float4*)&hb[(size_t)s1*HH + c4];
      float4 a2 = *(const float4*)&hb[(size_t)s2*HH + c4];
      float4 a3 = *(const float4*)&hb[(size_t)s3*HH + c4];
      s.x=fmaf(a0.x,w0,s.x); s.y=fmaf(a0.y,w0,s.y); s.z=fmaf(a0.z,w0,s.z); s.w=fmaf(a0.w,w0,s.w);
      s.x=fmaf(a1.x,w1,s.x); s.y=fmaf(a1.y,w1,s.y); s.z=fmaf(a1.z,w1,s.z); s.w=fmaf(a1.w,w1,s.w);
      s.x=fmaf(a2.x,w2,s.x); s.y=fmaf(a2.y,w2,s.y); s.z=fmaf(a2.z,w2,s.z); s.w=fmaf(a2.w,w2,s.w);
      s.x=fmaf(a3.x,w3,s.x); s.y=fmaf(a3.y,w3,s.y); s.z=fmaf(a3.z,w3,s.z); s.w=fmaf(a3.w,w3,s.w);
    }
    for (; i<end; i++){
      int sc=__ldg(&srcp[i]);
      float w=__ldg(&wwp[__ldg(&eidp[i])]);
      float4 a = *(const float4*)&hb[(size_t)sc*HH + c4];
      s.x=fmaf(a.x,w,s.x); s.y=fmaf(a.y,w,s.y); s.z=fmaf(a.z,w,s.z); s.w=fmaf(a.w,w,s.w);
    }
  } else {
    for (; i+4<=end; i+=4){
      int s0=__ldg(&srcp[i]),   s1=__ldg(&srcp[i+1]);
      int s2=__ldg(&srcp[i+2]), s3=__ldg(&srcp[i+3]);
      float4 a0 = *(const float4*)&hb[(size_t)s0*HH + c4];
      float4 a1 = *(const float4*)&hb[(size_t)s1*HH + c4];
      float4 a2 = *(const float4*)&hb[(size_t)s2*HH + c4];
      float4 a3 = *(const float4*)&hb[(size_t)s3*HH + c4];
      s.x+=a0.x; s.y+=a0.y; s.z+=a0.z; s.w+=a0.w;
      s.x+=a1.x; s.y+=a1.y; s.z+=a1.z; s.w+=a1.w;
      s.x+=a2.x; s.y+=a2.y; s.z+=a2.z; s.w+=a2.w;
      s.x+=a3.x; s.y+=a3.y; s.z+=a3.z; s.w+=a3.w;
    }
    for (; i<end; i++){
      int sc=__ldg(&srcp[i]);
      float4 a = *(const float4*)&hb[(size_t)sc*HH + c4];
      s.x+=a.x; s.y+=a.y; s.z+=a.z; s.w+=a.w;
    }
  }
  *(float4*)&g_A[(size_t)t_slot[e]*NN*HH + node*HH + c4] = s;
}

// M[slot] = A[slot] @ W[ki]; W column in registers
__global__ void __launch_bounds__(256) k_gemm(int rowOff, const float* wl){
  __shared__ float sW[4096];
  int e = rowOff + blockIdx.y;
  int ki = t_ki[e];
  int slot = t_slot[e];
  for (int i=threadIdx.x;i<4096;i+=256) sW[i] = wl[(size_t)ki*4096 + i];
  __syncthreads();
  int colt = threadIdx.x & 63;
  int rb   = threadIdx.x >> 6;
  float w[64];
  #pragma unroll
  for (int k=0;k<64;k++) w[k] = sW[k*64+colt];
  const float* Ab = g_A + (size_t)slot*NN*HH;
  float* Mb = g_M + (size_t)slot*NN*HH;
  int row0 = blockIdx.x*64;
  for (int q=0;q<16;q++){
    int row = row0 + q*4 + rb;
    const float4* Ar = (const float4*)&Ab[(size_t)row*HH];
    float acc = 0.f;
    #pragma unroll
    for (int k4=0;k4<16;k4++){
      float4 a = Ar[k4];
      acc = fmaf(a.x, w[4*k4+0], acc);
      acc = fmaf(a.y, w[4*k4+1], acc);
      acc = fmaf(a.z, w[4*k4+2], acc);
      acc = fmaf(a.w, w[4*k4+3], acc);
    }
    Mb[(size_t)row*HH + colt] = acc;
  }
}

// h_out = relu(base + sum M[slots])
__global__ void k_comb(int set, int baseSel, int outSel){
  int v = blockIdx.z, d = blockIdx.y;
  int i = blockIdx.x*256 + threadIdx.x;     // < NN*HH
  const float* base = (baseSel==0)? g_h0 : ((baseSel==1)? g_hl0 : g_hv + (size_t)v*5*NN*HH);
  float* outp = (outSel==0)? g_hl0 : ((outSel==1)? g_h1 : g_hv + (size_t)v*5*NN*HH);
  size_t off = (size_t)d*NN*HH + i;
  float s = base[off];
  int cnt = cmb_cnt[set][v][d];
  for (int j=0;j<cnt;j++)
    s += g_M[(size_t)cmb_slot[set][v][d][j]*NN*HH + i];
  outp[off] = fmaxf(s, 0.f);
}

// ---------------- edge sparsification (batched over 4 keys) ----------------

__global__ void k_uvB(const float* w_pred){
  int ki = blockIdx.y;
  int n = blockIdx.x*256 + threadIdx.x;
  if (n >= NN) return;
  const float* h = g_h1 + (size_t)ki*NN*HH + (size_t)n*HH;
  const float* wp = w_pred + ki*256;
  float a=0.f, b=0.f;
  for (int c=0;c<64;c++){
    float hv = h[c];
    a = fmaf(hv, wp[c*2],      a);
    b = fmaf(hv, wp[(64+c)*2], b);
  }
  g_uf[ki*NN+n]=a; g_vf[ki*NN+n]=b;
}

__global__ void k_predwB(EPtrs es, const float* b_pred){
  int ki = blockIdx.y;
  int j = blockIdx.x*256 + threadIdx.x;
  if (j >= EE) return;
  const int* ei = es.e[ki];
  int r = ei[j], c = ei[EE+j];
  g_epredf[(size_t)ki*EE + j] = (g_uf[ki*NN+r] + g_vf[ki*NN+c]) + b_pred[ki*2];
}

__global__ void k_selectB(){
  int ki = blockIdx.y;
  int r = blockIdx.x*128 + threadIdx.x;
  if (r >= NN) return;
  uint32_t fk0, fk1;
  threefry(0u, 42u, 0u, (uint32_t)ki, fk0, fk1);

  int beg = g_soff[ki*(NN+1)+r], end = g_soff[ki*(NN+1)+r+1];
  int n = end - beg; if (n > 192) n = 192;
  const int* pk = g_spk + (size_t)ki*EE;
  const float* ep = g_epredf + (size_t)ki*EE;

  int mcol[192]; float mlg[192]; int m = 0;
  int i = 0;
  while (i < n){
    int c = pk[beg+i] >> 17;
    float s = 0.f;
    while (i < n && (pk[beg+i]>>17) == c){
      s = s + ep[pk[beg+i] & 0x1FFFF];
      i++;
    }
    if (s > 0.0f){
      float g = gumbel_at(fk0, fk1, (uint32_t)r*4096u + (uint32_t)c);
      mcol[m] = c;
      mlg[m]  = s + g;
      m++;
    }
  }
  int tc = 0; int tcol[16]; float te[16];
  if (m > 0){
    float mx = mlg[0];
    for (int q=1;q<m;q++) mx = fmaxf(mx, mlg[q]);
    for (int q=0;q<m;q++){
      float E = expf(mlg[q]-mx);
      int C = mcol[q];
      if (tc==16 && !(E > te[15])) continue;
      int pos = (tc<16) ? tc++ : 15;
      while (pos>0 && te[pos-1] < E){ te[pos]=te[pos-1]; tcol[pos]=tcol[pos-1]; pos--; }
      te[pos]=E; tcol[pos]=C;
    }
  }
  int cut = -1;
  if (m < 16){
    int X = (16 - m) - 1;
    for (int q=0;q<m;q++) if (mcol[q] <= X) X++;
    cut = X;
  }
  g_selcnt[ki*NN+r] = tc;
  g_cutoff[ki*NN+r] = cut;
  for (int j=0;j<tc;j++) g_selcol[(ki*NN+r)*16+j] = tcol[j];
}

__global__ void k_edgewB(EPtrs es, float* out){
  int ki = blockIdx.y;
  int j = blockIdx.x*256 + threadIdx.x;
  if (j >= EE) return;
  const int* ei = es.e[ki];
  int r = ei[j], c = ei[EE+j];
  int cnt = g_selcnt[ki*NN+r];
  float w = 0.f;
  const int* sc = &g_selcol[(ki*NN+r)*16];
  for (int q=0;q<cnt;q++) if (sc[q] == c){ w = 1.0f; break; }
  if (w == 0.f && c <= g_cutoff[ki*NN+r]) w = 1.0f;
  g_ww[(size_t)ki*EE + j] = w;
  out[WOFF + (size_t)ki*EE + j] = w;
}

// ---------------- outputs ----------------

__global__ void k_pool(const int* idxp, const float* w_cls, const float* b_cls, float* out){
  __shared__ float p[64];
  __shared__ float lg[8];
  int t = threadIdx.x;
  int idx = *idxp;
  float v = g_hv[0*5*NN*HH + 1*NN*HH + (size_t)idx*HH + t];
  p[t] = v;
  out[POOLOFF + t] = v;
  __syncthreads();
  if (t < 8){
    float a = 0.f;
    for (int c=0;c<64;c++) a = fmaf(p[c], w_cls[c*8+t], a);
    lg[t] = a + b_cls[t];
  }
  __syncthreads();
  if (t == 0){
    float mx = lg[0];
    for (int i2=1;i2<8;i2++) mx = fmaxf(mx, lg[i2]);
    float Z = 0.f, ex[8];
    for (int i2=0;i2<8;i2++){ ex[i2] = expf(lg[i2]-mx); Z += ex[i2]; }
    for (int i2=0;i2<8;i2++) out[i2] = ex[i2]/Z;
  }
}

__global__ void k_srcpool(const int* idxp, float* out){
  int t = threadIdx.x;
  int idx = *idxp;
  out[SRCOFF + t] = g_hv[2*5*NN*HH + 1*NN*HH + (size_t)idx*HH + t];
}

__global__ void k_nodesub(IPtrs5 bs, float* out){
  int d = blockIdx.x >> 4;
  int g = blockIdx.x & 15;
  int c = threadIdx.x;
  const int* b = bs.p[d];
  int lo=0, hi=NN;
  while (lo<hi){ int mid=(lo+hi)>>1; if (b[mid]< g) lo=mid+1; else hi=mid; }
  int st = lo;
  lo=0; hi=NN;
  while (lo<hi){ int mid=(lo+hi)>>1; if (b[mid]<=g) lo=mid+1; else hi=mid; }
  int en = lo;
  const float* hb = g_hv + 1*5*NN*HH + (size_t)d*NN*HH;
  float acc = 0.f;
  for (int nn2=st; nn2<en; nn2++) acc += hb[(size_t)nn2*HH + c];
  out[NSOFF + (d*16+g)*64 + c] = acc;
}

// ---------------- host ----------------

extern "C" void kernel_launch(void* const* d_in, const int* in_sizes, int n_in,
                              void* d_out, int out_size){
  Ptrs5 xs;  for (int i=0;i<5;i++)  xs.p[i] = (const float*)d_in[i];
  EPtrs es;  for (int i=0;i<10;i++) es.e[i] = (const int*)d_in[5+i];
  IPtrs5 bb; for (int i=0;i<5;i++)  bb.p[i] = (const int*)d_in[15+i];
  const int*   idxp   = (const int*)  d_in[20];
  const float* w_in   = (const float*)d_in[21];
  const float* b_in   = (const float*)d_in[22];
  const float* w_msg  = (const float*)d_in[23];
  const float* w_pred = (const float*)d_in[24];
  const float* b_pred = (const float*)d_in[25];
  const float* w_cls  = (const float*)d_in[26];
  const float* b_cls  = (const float*)d_in[27];
  float* out = (float*)d_out;
  const float* wL0 = w_msg;
  const float* wL1 = w_msg + 10*64*64;

  // unified CSR build (10 agg + 4 sel)
  k_zeroAll<<<160,256>>>();
  k_countAll<<<dim3(512,14),256>>>(es);
  k_scanAll<<<14,1024>>>();
  k_binAll<<<dim3(512,14),256>>>(es);
  k_sortAll<<<dim3(16,14),256>>>();

  // input transform
  k_input<<<dim3(256,5),256>>>(xs, w_in, b_in);

  // Phase A: h1
  k_aggU<<<dim3(256,4),256>>>(0);
  k_gemm<<<dim3(64,4),256>>>(0, wL0);
  k_comb<<<dim3(1024,5,1),256>>>(0, 0, 0);
  k_aggU<<<dim3(256,4),256>>>(4);
  k_gemm<<<dim3(64,4),256>>>(4, wL1);
  k_comb<<<dim3(1024,5,1),256>>>(1, 1, 1);

  // edge sparsification
  k_uvB<<<dim3(16,4),256>>>(w_pred);
  k_predwB<<<dim3(512,4),256>>>(es, b_pred);
  k_selectB<<<dim3(32,4),128>>>();
  k_edgewB<<<dim3(512,4),256>>>(es, out);

  // Phase B layer 0
  k_aggU<<<dim3(256,10),256>>>(8);
  k_gemm<<<dim3(64,10),256>>>(8, wL0);
  k_comb<<<dim3(1024,5,3),256>>>(2, 0, 2);

  // Phase B layer 1
  k_aggU<<<dim3(256,24),256>>>(18);
  k_gemm<<<dim3(64,24),256>>>(18, wL1);
  k_comb<<<dim3(1024,5,3),256>>>(3, 2, 2);

  // outputs
  k_pool<<<1,64>>>(idxp, w_cls, b_cls, out);
  k_nodesub<<<80,64>>>(bb, out);
  k_srcpool<<<1,64>>>(idxp, out);
}